// round 2
// baseline (speedup 1.0000x reference)
#include <cuda_runtime.h>

#define NBATCH 16
#define NF     128
#define NT     4096
#define NS     4
#define TPB    1024
#define PT     4     // elements per thread: TPB*PT == NT

__device__ __forceinline__ float fast_exp2(float x) {
    float r;
    asm("ex2.approx.ftz.f32 %0, %1;" : "=f"(r) : "f"(x));
    return r;
}
__device__ __forceinline__ float fast_log2(float x) {
    float r;
    asm("lg2.approx.ftz.f32 %0, %1;" : "=f"(r) : "f"(x));
    return r;
}

__global__ __launch_bounds__(TPB, 2)
void mrpcen_kernel(const float* __restrict__ x,
                   const float* __restrict__ alpha_log,
                   const float* __restrict__ delta_log,
                   const float* __restrict__ r_log,
                   float* __restrict__ out)
{
    const int si  = blockIdx.x;          // smoother rate index (0..3)
    const int row = blockIdx.y;          // b*NF + f
    const int f   = row & (NF - 1);
    const int b   = row >> 7;
    const int tid = threadIdx.x;
    const int lane = tid & 31;
    const int w    = tid >> 5;

    // s for this rate (compile-time problem constants, fp32 like the reference)
    float s, a;
    {
        const float tv[NS] = {0.015f, 0.06f, 0.25f, 1.0f};
        float tt = tv[si] * (44100.0f / 512.0f);
        float d2 = 2.0f * tt * tt;
        s = (sqrtf(1.0f + 2.0f * d2) - 1.0f) / d2;
        a = 1.0f - s;
    }
    const float a2 = a * a;
    const float a4 = a2 * a2;                // per-thread chain decay (PT=4)

    const float al    = alpha_log[f];
    const float dl    = delta_log[f];
    const float rl    = r_log[f];
    const float alpha = __expf(al);
    const float delta = __expf(dl);
    const float rr    = __expf(rl);
    const float delta_r = __expf(rr * dl);   // delta^r

    // ---- perfectly coalesced load: lane stride = 16B ----
    const float* xrow = x + (size_t)row * NT;
    float4 xv4 = *reinterpret_cast<const float4*>(xrow + tid * PT);
    float xv[PT] = {xv4.x, xv4.y, xv4.z, xv4.w};

    // ---- local recurrence with m_in = 0 -> scalar carry b ----
    float bcar = 0.0f;
#pragma unroll
    for (int k = 0; k < PT; k++)
        bcar = fmaf(a, bcar, s * xv[k]);

    // fold global boundary (m[0] = x[0]  <=>  m_in = x[0], since a+s==1)
    if (tid == 0)
        bcar = fmaf(a4, xv[0], bcar);

    // ---- warp-level constant-coefficient inclusive scan (register only) ----
    // b_inc[l] = sum_{j<=l} a^{4(l-j)} b[j];  step-d coefficient = a^(4d)
    {
        float c = a4;
#pragma unroll
        for (int d = 1; d <= 16; d <<= 1) {
            float up = __shfl_up_sync(0xffffffffu, bcar, d);
            if (lane >= d) bcar = fmaf(c, up, bcar);
            c = c * c;
        }
    }

    // ---- cross-warp scan of 32 warp aggregates (coefficient a^128) ----
    __shared__ float wsum[TPB / 32];
    if (lane == 31) wsum[w] = bcar;
    __syncthreads();
    if (w == 0) {
        float v = wsum[lane];
        float c128;   // a^128 = (a^4)^32
        {
            float t = a4;                 // a^4
            t = t * t;  t = t * t;        // a^16, ... wait: square 3 times
            t = t * t;                    // a^32
            c128 = t * t * (t * t);       // (a^32)^2 * (a^32)^2 = a^128
        }
        float c = c128;
#pragma unroll
        for (int d = 1; d <= 16; d <<= 1) {
            float up = __shfl_up_sync(0xffffffffu, v, d);
            if (lane >= d) v = fmaf(c, up, v);
            c = c * c;
        }
        wsum[lane] = v;   // inclusive prefix P[w]
    }
    __syncthreads();

    // ---- per-thread incoming state m_in ----
    const float wprefix = (w > 0) ? wsum[w - 1] : 0.0f;
    const float Lprev   = __shfl_up_sync(0xffffffffu, bcar, 1);  // local incl of lane-1
    float m;
    if (tid == 0) {
        m = xv[0];                       // boundary: m_in = x[0]
    } else if (lane == 0) {
        m = wprefix;
    } else {
        // a^(4*lane) via exp2(4*lane*log2(a))
        float a4l = fast_exp2((float)(4 * lane) * fast_log2(a));
        m = fmaf(a4l, wprefix, Lprev);
    }

    // ---- pass 2: recurrence + fused PCEN, coalesced float4 store ----
    float tmp[PT];
#pragma unroll
    for (int k = 0; k < PT; k++) {
        m = fmaf(a, m, s * xv[k]);
        const float u  = 1e-5f + m;                         // eps + m
        const float sm = fast_exp2(-alpha * fast_log2(u));  // (eps+m)^-alpha
        const float v2 = fmaf(xv[k], sm, delta);            // x*smooth + delta
        tmp[k] = fast_exp2(rr * fast_log2(v2)) - delta_r;   // v^r - delta^r
    }
    float* orow = out + ((((size_t)b * NS + si) * NF + f) * (size_t)NT) + (size_t)tid * PT;
    float4 o;
    o.x = tmp[0]; o.y = tmp[1]; o.z = tmp[2]; o.w = tmp[3];
    *reinterpret_cast<float4*>(orow) = o;
}

extern "C" void kernel_launch(void* const* d_in, const int* in_sizes, int n_in,
                              void* d_out, int out_size) {
    const float* x         = (const float*)d_in[0];
    const float* alpha_log = (const float*)d_in[1];
    const float* delta_log = (const float*)d_in[2];
    const float* r_log     = (const float*)d_in[3];
    float* out             = (float*)d_out;
    (void)in_sizes; (void)n_in; (void)out_size;

    dim3 grid(NS, NBATCH * NF);   // si fast dim -> 4 blocks of same row adjacent (L2 reuse of x)
    dim3 block(TPB);
    mrpcen_kernel<<<grid, block>>>(x, alpha_log, delta_log, r_log, out);
}

// round 3
// speedup vs baseline: 2.5597x; 2.5597x over previous
#include <cuda_runtime.h>

#define NBATCH 16
#define NF     128
#define NT     4096
#define NS     4
#define TPB    256
#define PT     16          // TPB*PT == NT
#define GP     20          // padded group stride (16 data + 4 pad floats)
#define BUFSZ  (TPB * GP)  // 5120 floats = 20KB

__device__ __forceinline__ float fast_exp2(float x) {
    float r; asm("ex2.approx.ftz.f32 %0, %1;" : "=f"(r) : "f"(x)); return r;
}
__device__ __forceinline__ float fast_log2(float x) {
    float r; asm("lg2.approx.ftz.f32 %0, %1;" : "=f"(r) : "f"(x)); return r;
}

// padded smem float-address of logical element quad Q (elements 4Q..4Q+3)
__device__ __forceinline__ int qaddr(int Q) { return (Q >> 2) * GP + (Q & 3) * 4; }

__global__ __launch_bounds__(TPB, 5)
void mrpcen_kernel(const float* __restrict__ x,
                   const float* __restrict__ alpha_log,
                   const float* __restrict__ delta_log,
                   const float* __restrict__ r_log,
                   float* __restrict__ out)
{
    const int row  = blockIdx.x;        // b*NF + f
    const int f    = row & (NF - 1);
    const int b    = row >> 7;
    const int tid  = threadIdx.x;
    const int lane = tid & 31;
    const int w    = tid >> 5;

    __shared__ float buf[2][BUFSZ];
    __shared__ float wagg[NS][TPB / 32];

    // ---- problem-constant smoother coefficients (f32, as in reference) ----
    float s[NS], a[NS], a16[NS];
    {
        const float tv[NS] = {0.015f, 0.06f, 0.25f, 1.0f};
#pragma unroll
        for (int i = 0; i < NS; i++) {
            float tt = tv[i] * (44100.0f / 512.0f);
            float d2 = 2.0f * tt * tt;
            s[i] = (sqrtf(1.0f + 2.0f * d2) - 1.0f) / d2;
            a[i] = 1.0f - s[i];
            float t2 = a[i] * a[i], t4 = t2 * t2, t8 = t4 * t4;
            a16[i] = t8 * t8;
        }
    }

    const float al    = alpha_log[f];
    const float dl    = delta_log[f];
    const float rl    = r_log[f];
    const float alpha = __expf(al);
    const float delta = __expf(dl);
    const float rr    = __expf(rl);
    const float delta_r = __expf(rr * dl);

    // ---- stage x: coalesced LDG.128 -> padded smem ----
    const float* xrow = x + (size_t)row * NT;
#pragma unroll
    for (int j = 0; j < 4; j++) {
        int Q = j * TPB + tid;
        float4 v = *reinterpret_cast<const float4*>(xrow + 4 * Q);
        *reinterpret_cast<float4*>(&buf[0][qaddr(Q)]) = v;
    }
    __syncthreads();

    // each thread pulls its 16 contiguous elements (own padded group)
    float xv[PT];
#pragma unroll
    for (int q = 0; q < 4; q++) {
        float4 v = *reinterpret_cast<float4*>(&buf[0][tid * GP + q * 4]);
        xv[4 * q + 0] = v.x; xv[4 * q + 1] = v.y;
        xv[4 * q + 2] = v.z; xv[4 * q + 3] = v.w;
    }
    // (no sync needed: each thread only rewrites its OWN group below)

    // ---- pass 1 + register scans, all 4 rates ----
    float bc[NS];
#pragma unroll
    for (int si = 0; si < NS; si++) {
        float bcar = 0.0f;
#pragma unroll
        for (int k = 0; k < PT; k++)
            bcar = fmaf(a[si], bcar, s[si] * xv[k]);
        if (tid == 0)                       // fold m[0]=x[0] boundary (a+s==1)
            bcar = fmaf(a16[si], xv[0], bcar);
        float c = a16[si];
#pragma unroll
        for (int d = 1; d <= 16; d <<= 1) {
            float up = __shfl_up_sync(0xffffffffu, bcar, d);
            if (lane >= d) bcar = fmaf(c, up, bcar);
            c = c * c;
        }
        bc[si] = bcar;
        if (lane == 31) wagg[si][w] = bcar;
    }
    __syncthreads();

    // ---- cross-warp: one segmented 32-lane scan handles 4 rates x 8 warps ----
    if (w == 0) {
        const int gsi = lane >> 3, gl = lane & 7;
        float v = wagg[gsi][gl];
        // recompute a_gsi^512 = (a^16)^32
        float tt = (gsi == 0) ? (0.015f * (44100.0f / 512.0f)) :
                   (gsi == 1) ? (0.06f  * (44100.0f / 512.0f)) :
                   (gsi == 2) ? (0.25f  * (44100.0f / 512.0f)) :
                                (1.0f   * (44100.0f / 512.0f));
        float d2 = 2.0f * tt * tt;
        float aa = 1.0f - (sqrtf(1.0f + 2.0f * d2) - 1.0f) / d2;
        float c = aa;
#pragma unroll
        for (int i = 0; i < 9; i++) c = c * c;   // a^512
#pragma unroll
        for (int d = 1; d <= 4; d <<= 1) {
            float up = __shfl_up_sync(0xffffffffu, v, d);
            if (gl >= d) v = fmaf(c, up, v);
            c = c * c;
        }
        wagg[gsi][gl] = v;                       // inclusive warp prefix
    }
    __syncthreads();

    // ---- per-thread incoming state for each rate ----
    float minv[NS];
#pragma unroll
    for (int si = 0; si < NS; si++) {
        float Lprev = __shfl_up_sync(0xffffffffu, bc[si], 1);
        if (tid == 0) {
            minv[si] = xv[0];
        } else {
            float P = (w > 0) ? wagg[si][w - 1] : 0.0f;
            float a16l = fast_exp2((float)(16 * lane) * fast_log2(a[si]));
            minv[si] = fmaf(a16l, P, (lane > 0) ? Lprev : 0.0f);
        }
    }

    // ---- pass 2: recurrence + fused PCEN, staged coalesced stores ----
    const float log_eps_neg = 1e-5f;
#pragma unroll
    for (int si = 0; si < NS; si++) {
        float m = minv[si];
        float* sb = buf[si & 1];
#pragma unroll
        for (int q = 0; q < 4; q++) {
            float t4[4];
#pragma unroll
            for (int e = 0; e < 4; e++) {
                const int k = q * 4 + e;
                m = fmaf(a[si], m, s[si] * xv[k]);
                const float u  = log_eps_neg + m;                   // eps + m
                const float sm = fast_exp2(-alpha * fast_log2(u));  // (eps+m)^-alpha
                const float v2 = fmaf(xv[k], sm, delta);
                t4[e] = fast_exp2(rr * fast_log2(v2)) - delta_r;
            }
            float4 o; o.x = t4[0]; o.y = t4[1]; o.z = t4[2]; o.w = t4[3];
            *reinterpret_cast<float4*>(&sb[tid * GP + q * 4]) = o;  // own group
        }
        __syncthreads();
        float* orow = out + (((size_t)b * NS + si) * NF + f) * (size_t)NT;
#pragma unroll
        for (int j = 0; j < 4; j++) {
            int Q = j * TPB + tid;
            float4 v = *reinterpret_cast<float4*>(&sb[qaddr(Q)]);
            *reinterpret_cast<float4*>(orow + 4 * Q) = v;           // coalesced STG.128
        }
        // double-buffered: next rate writes the other buffer; the next rate's
        // barrier orders this rate's reads before buffer reuse two rates later
    }
}

extern "C" void kernel_launch(void* const* d_in, const int* in_sizes, int n_in,
                              void* d_out, int out_size) {
    const float* x         = (const float*)d_in[0];
    const float* alpha_log = (const float*)d_in[1];
    const float* delta_log = (const float*)d_in[2];
    const float* r_log     = (const float*)d_in[3];
    float* out             = (float*)d_out;
    (void)in_sizes; (void)n_in; (void)out_size;

    dim3 grid(NBATCH * NF);   // 2048 blocks: one per (b, f) row
    dim3 block(TPB);
    mrpcen_kernel<<<grid, block>>>(x, alpha_log, delta_log, r_log, out);
}